// round 2
// baseline (speedup 1.0000x reference)
#include <cuda_runtime.h>
#include <math.h>

#define F_IN  128
#define NH1   8
#define C1    32
#define HID   256
#define NCLS  40
#define NEGS  0.2f
#define MAXN  100000
#define MAXET 900000

#define NEG_INF __int_as_float(0xff800000)

// ---------------- scratch (static device globals; no allocation) ----------------
__device__ __align__(16) float g_h1 [(size_t)MAXN * HID];   // layer1 transformed features
__device__ __align__(16) float g_out1[(size_t)MAXN * HID];  // layer1 aggregated output (then elu'd)
__device__ __align__(16) float g_as1[MAXN * NH1];
__device__ __align__(16) float g_ad1[MAXN * NH1];
__device__ __align__(16) float g_m1 [MAXN * NH1];
__device__ __align__(16) float g_den1[MAXN * NH1];
__device__ __align__(16) float g_e1 [(size_t)MAXET * NH1];
__device__ __align__(16) float g_h2 [(size_t)MAXN * NCLS];
__device__ __align__(16) float g_as2[MAXN];
__device__ __align__(16) float g_ad2[MAXN];
__device__ __align__(16) float g_m2 [MAXN];
__device__ __align__(16) float g_den2[MAXN];
__device__ __align__(16) float g_e2 [MAXET];

// monotone float atomic max via signed/unsigned int atomics (works for mixed signs,
// init = -inf). Avg contention ~9/node -> negligible.
__device__ __forceinline__ void atomicMaxF(float* addr, float v) {
    if (v >= 0.f) atomicMax((int*)addr, __float_as_int(v));
    else          atomicMin((unsigned int*)addr, __float_as_uint(v));
}

// ---------------- init ----------------
__global__ void init_kernel(float* __restrict__ out, int N) {
    int stride = gridDim.x * blockDim.x;
    int i0 = blockIdx.x * blockDim.x + threadIdx.x;
    for (int i = i0; i < N * HID; i += stride) g_out1[i] = 0.f;
    for (int i = i0; i < N * NH1; i += stride) { g_m1[i] = NEG_INF; g_den1[i] = 0.f; }
    for (int i = i0; i < N;       i += stride) { g_m2[i] = NEG_INF; g_den2[i] = 0.f; }
    for (int i = i0; i < N * NCLS; i += stride) out[i] = 0.f;
}

// ---------------- tiled fp32 GEMM: C[M,NC] = A[M,K] @ B[K,NC] ----------------
// BM=128, BN=64, BK=16, 256 threads, TM=8, TN=4.
// SEL=0: A=Ain (x),     C=g_h1
// SEL=1: A=g_out1,      C=g_h2
template<int K, int NC, int SEL>
__global__ void gemm_kernel(const float* __restrict__ Ain, const float* __restrict__ B, int M) {
    const float* A = (SEL == 0) ? Ain : g_out1;
    float*       C = (SEL == 0) ? g_h1 : g_h2;
    __shared__ float As[16][132];  // [k][m], padded
    __shared__ float Bs[16][68];   // [k][n], padded
    const int t  = threadIdx.x;
    const int tx = t & 15;
    const int ty = t >> 4;
    const int rowBase = blockIdx.y * 128;
    const int colBase = blockIdx.x * 64;
    float acc[8][4];
    #pragma unroll
    for (int i = 0; i < 8; i++)
        #pragma unroll
        for (int j = 0; j < 4; j++) acc[i][j] = 0.f;

    for (int k0 = 0; k0 < K; k0 += 16) {
        // A tile: 128 rows x 16 k — 2 float4 per thread
        #pragma unroll
        for (int i = 0; i < 2; i++) {
            int idx = t * 2 + i;
            int r  = idx >> 2;
            int kk = (idx & 3) * 4;
            float4 v = make_float4(0.f, 0.f, 0.f, 0.f);
            int grow = rowBase + r;
            if (grow < M) v = *(const float4*)&A[(size_t)grow * K + k0 + kk];
            As[kk+0][r] = v.x; As[kk+1][r] = v.y; As[kk+2][r] = v.z; As[kk+3][r] = v.w;
        }
        // B tile: 16 k x 64 cols — 1 float4 per thread
        {
            int r  = t >> 4;
            int cc = (t & 15) * 4;
            float4 v = make_float4(0.f, 0.f, 0.f, 0.f);
            if (colBase + cc < NC)
                v = *(const float4*)&B[(size_t)(k0 + r) * NC + colBase + cc];
            *(float4*)&Bs[r][cc] = v;
        }
        __syncthreads();
        #pragma unroll
        for (int kk = 0; kk < 16; kk++) {
            float4 a0 = *(const float4*)&As[kk][ty * 8];
            float4 a1 = *(const float4*)&As[kk][ty * 8 + 4];
            float4 bv = *(const float4*)&Bs[kk][tx * 4];
            float a[8] = {a0.x, a0.y, a0.z, a0.w, a1.x, a1.y, a1.z, a1.w};
            float b[4] = {bv.x, bv.y, bv.z, bv.w};
            #pragma unroll
            for (int i = 0; i < 8; i++)
                #pragma unroll
                for (int j = 0; j < 4; j++)
                    acc[i][j] = fmaf(a[i], b[j], acc[i][j]);
        }
        __syncthreads();
    }
    #pragma unroll
    for (int i = 0; i < 8; i++) {
        int r = rowBase + ty * 8 + i;
        if (r >= M) continue;
        int c = colBase + tx * 4;
        if (c < NC)
            *(float4*)&C[(size_t)r * NC + c] =
                make_float4(acc[i][0], acc[i][1], acc[i][2], acc[i][3]);
    }
}

// ---------------- layer1 attention coefficients ----------------
// idx = n*8 + h; g_h1[idx*32 ..] is exactly node n, head h's 32 channels.
__global__ void alpha1_kernel(const float* __restrict__ a_src, const float* __restrict__ a_dst, int N) {
    int idx = blockIdx.x * blockDim.x + threadIdx.x;
    if (idx >= N * NH1) return;
    int h = idx & 7;
    const float* row = &g_h1[(size_t)idx * C1];
    float s = 0.f, d = 0.f;
    #pragma unroll
    for (int c = 0; c < C1; c += 4) {
        float4 v  = *(const float4*)&row[c];
        float4 ws = *(const float4*)&a_src[h * C1 + c];
        float4 wd = *(const float4*)&a_dst[h * C1 + c];
        s += v.x*ws.x + v.y*ws.y + v.z*ws.z + v.w*ws.w;
        d += v.x*wd.x + v.y*wd.y + v.z*wd.z + v.w*wd.w;
    }
    g_as1[idx] = s; g_ad1[idx] = d;
}

__global__ void edge_max1_kernel(const int* __restrict__ ei, int E, int ET) {
    int e = blockIdx.x * blockDim.x + threadIdx.x;
    if (e >= ET) return;
    int s, d;
    if (e < E) { s = ei[e]; d = ei[E + e]; } else { s = e - E; d = s; }
    float4 s0 = *(const float4*)&g_as1[s * NH1];
    float4 s1 = *(const float4*)&g_as1[s * NH1 + 4];
    float4 d0 = *(const float4*)&g_ad1[d * NH1];
    float4 d1 = *(const float4*)&g_ad1[d * NH1 + 4];
    float v[8] = {s0.x+d0.x, s0.y+d0.y, s0.z+d0.z, s0.w+d0.w,
                  s1.x+d1.x, s1.y+d1.y, s1.z+d1.z, s1.w+d1.w};
    #pragma unroll
    for (int h = 0; h < 8; h++) {
        v[h] = v[h] >= 0.f ? v[h] : NEGS * v[h];
        atomicMaxF(&g_m1[d * NH1 + h], v[h]);
    }
    *(float4*)&g_e1[(size_t)e * NH1]     = make_float4(v[0], v[1], v[2], v[3]);
    *(float4*)&g_e1[(size_t)e * NH1 + 4] = make_float4(v[4], v[5], v[6], v[7]);
}

__global__ void edge_exp1_kernel(const int* __restrict__ ei, int E, int ET) {
    int e = blockIdx.x * blockDim.x + threadIdx.x;
    if (e >= ET) return;
    int d = (e < E) ? ei[E + e] : e - E;
    float4 v0 = *(const float4*)&g_e1[(size_t)e * NH1];
    float4 v1 = *(const float4*)&g_e1[(size_t)e * NH1 + 4];
    float4 m0 = *(const float4*)&g_m1[d * NH1];
    float4 m1 = *(const float4*)&g_m1[d * NH1 + 4];
    float ex[8] = {expf(v0.x - m0.x), expf(v0.y - m0.y), expf(v0.z - m0.z), expf(v0.w - m0.w),
                   expf(v1.x - m1.x), expf(v1.y - m1.y), expf(v1.z - m1.z), expf(v1.w - m1.w)};
    #pragma unroll
    for (int h = 0; h < 8; h++) atomicAdd(&g_den1[d * NH1 + h], ex[h]);
    *(float4*)&g_e1[(size_t)e * NH1]     = make_float4(ex[0], ex[1], ex[2], ex[3]);
    *(float4*)&g_e1[(size_t)e * NH1 + 4] = make_float4(ex[4], ex[5], ex[6], ex[7]);
}

// warp per edge: lane handles channel k*32+lane (head k), alpha broadcast via shfl.
__global__ void edge_agg1_kernel(const int* __restrict__ ei, int E, int ET) {
    int w = (blockIdx.x * blockDim.x + threadIdx.x) >> 5;
    int lane = threadIdx.x & 31;
    if (w >= ET) return;
    int s, d;
    if (w < E) { s = ei[w]; d = ei[E + w]; } else { s = w - E; d = s; }
    float alpha = 0.f;
    if (lane < NH1) alpha = g_e1[(size_t)w * NH1 + lane] / (g_den1[d * NH1 + lane] + 1e-16f);
    const float* hrow = &g_h1 [(size_t)s * HID];
    float*       orow = &g_out1[(size_t)d * HID];
    #pragma unroll
    for (int k = 0; k < NH1; k++) {
        float ak = __shfl_sync(0xffffffffu, alpha, k);
        atomicAdd(&orow[k * 32 + lane], ak * hrow[k * 32 + lane]);
    }
}

__global__ void elu_kernel(const float* __restrict__ b1, int N) {
    int i = blockIdx.x * blockDim.x + threadIdx.x;
    if (i >= N * HID) return;
    float v = g_out1[i] + b1[i & (HID - 1)];
    g_out1[i] = v > 0.f ? v : expm1f(v);
}

// ---------------- layer 2 ----------------
__global__ void alpha2_kernel(const float* __restrict__ a_src, const float* __restrict__ a_dst, int N) {
    int n = blockIdx.x * blockDim.x + threadIdx.x;
    if (n >= N) return;
    const float* row = &g_h2[(size_t)n * NCLS];
    float s = 0.f, d = 0.f;
    #pragma unroll
    for (int c = 0; c < NCLS; c += 4) {
        float4 v  = *(const float4*)&row[c];
        float4 ws = *(const float4*)&a_src[c];
        float4 wd = *(const float4*)&a_dst[c];
        s += v.x*ws.x + v.y*ws.y + v.z*ws.z + v.w*ws.w;
        d += v.x*wd.x + v.y*wd.y + v.z*wd.z + v.w*wd.w;
    }
    g_as2[n] = s; g_ad2[n] = d;
}

__global__ void edge_max2_kernel(const int* __restrict__ ei, int E, int ET) {
    int e = blockIdx.x * blockDim.x + threadIdx.x;
    if (e >= ET) return;
    int s, d;
    if (e < E) { s = ei[e]; d = ei[E + e]; } else { s = e - E; d = s; }
    float v = g_as2[s] + g_ad2[d];
    v = v >= 0.f ? v : NEGS * v;
    g_e2[e] = v;
    atomicMaxF(&g_m2[d], v);
}

__global__ void edge_exp2_kernel(const int* __restrict__ ei, int E, int ET) {
    int e = blockIdx.x * blockDim.x + threadIdx.x;
    if (e >= ET) return;
    int d = (e < E) ? ei[E + e] : e - E;
    float ex = expf(g_e2[e] - g_m2[d]);
    g_e2[e] = ex;
    atomicAdd(&g_den2[d], ex);
}

__global__ void edge_agg2_kernel(const int* __restrict__ ei, int E, int ET,
                                 float* __restrict__ out) {
    int w = (blockIdx.x * blockDim.x + threadIdx.x) >> 5;
    int lane = threadIdx.x & 31;
    if (w >= ET) return;
    int s, d;
    if (w < E) { s = ei[w]; d = ei[E + w]; } else { s = w - E; d = s; }
    float alpha = g_e2[w] / (g_den2[d] + 1e-16f);
    const float* hrow = &g_h2[(size_t)s * NCLS];
    float*       orow = &out [(size_t)d * NCLS];
    for (int c = lane; c < NCLS; c += 32)
        atomicAdd(&orow[c], alpha * hrow[c]);
}

// warp per node; lane covers class lane and lane+32 (lane<8).
__global__ void logsoftmax_kernel(float* __restrict__ out, const float* __restrict__ b2, int N) {
    int w = (blockIdx.x * blockDim.x + threadIdx.x) >> 5;
    int lane = threadIdx.x & 31;
    if (w >= N) return;
    float* row = &out[(size_t)w * NCLS];
    float a = row[lane] + b2[lane];
    float b = NEG_INF;
    if (lane < NCLS - 32) b = row[32 + lane] + b2[32 + lane];
    float mx = fmaxf(a, b);
    #pragma unroll
    for (int o = 16; o > 0; o >>= 1) mx = fmaxf(mx, __shfl_xor_sync(0xffffffffu, mx, o));
    float se = expf(a - mx) + (lane < NCLS - 32 ? expf(b - mx) : 0.f);
    #pragma unroll
    for (int o = 16; o > 0; o >>= 1) se += __shfl_xor_sync(0xffffffffu, se, o);
    float l = logf(se);
    row[lane] = a - mx - l;
    if (lane < NCLS - 32) row[32 + lane] = b - mx - l;
}

// ---------------- launch ----------------
extern "C" void kernel_launch(void* const* d_in, const int* in_sizes, int n_in,
                              void* d_out, int out_size) {
    const float* x      = (const float*)d_in[0];
    const int*   ei     = (const int*)d_in[1];   // jax int64 silently -> int32 (x64 disabled)
    const float* W1     = (const float*)d_in[2];
    const float* a_src1 = (const float*)d_in[3];
    const float* a_dst1 = (const float*)d_in[4];
    const float* b1     = (const float*)d_in[5];
    const float* W2     = (const float*)d_in[6];
    const float* a_src2 = (const float*)d_in[7];
    const float* a_dst2 = (const float*)d_in[8];
    const float* b2     = (const float*)d_in[9];
    float* out = (float*)d_out;

    int N  = in_sizes[0] / F_IN;
    int E  = in_sizes[1] / 2;
    int ET = E + N;   // + self loops

    init_kernel<<<2048, 256>>>(out, N);

    // ---- layer 1 ----
    {
        dim3 g((HID + 63) / 64, (N + 127) / 128);
        gemm_kernel<F_IN, HID, 0><<<g, 256>>>(x, W1, N);
    }
    alpha1_kernel<<<(N * NH1 + 255) / 256, 256>>>(a_src1, a_dst1, N);
    edge_max1_kernel<<<(ET + 255) / 256, 256>>>(ei, E, ET);
    edge_exp1_kernel<<<(ET + 255) / 256, 256>>>(ei, E, ET);
    edge_agg1_kernel<<<(int)(((long long)ET * 32 + 255) / 256), 256>>>(ei, E, ET);
    elu_kernel<<<(N * HID + 255) / 256, 256>>>(b1, N);

    // ---- layer 2 ----
    {
        dim3 g((NCLS + 63) / 64, (N + 127) / 128);
        gemm_kernel<HID, NCLS, 1><<<g, 256>>>(nullptr, W2, N);
    }
    alpha2_kernel<<<(N + 255) / 256, 256>>>(a_src2, a_dst2, N);
    edge_max2_kernel<<<(ET + 255) / 256, 256>>>(ei, E, ET);
    edge_exp2_kernel<<<(ET + 255) / 256, 256>>>(ei, E, ET);
    edge_agg2_kernel<<<(int)(((long long)ET * 32 + 255) / 256), 256>>>(ei, E, ET, out);
    logsoftmax_kernel<<<(int)(((long long)N * 32 + 255) / 256), 256>>>(out, b2, N);
}

// round 3
// speedup vs baseline: 1.5539x; 1.5539x over previous
#include <cuda_runtime.h>
#include <math.h>

#define F_IN  128
#define NH1   8
#define C1    32
#define HID   256
#define NCLS  40
#define NEGS  0.2f
#define MAXN  100000
#define MAXET 900000

#define NEG_INF __int_as_float(0xff800000)

// ---------------- scratch (static device globals; no allocation) ----------------
__device__ __align__(16) float g_h1 [(size_t)MAXN * HID];   // layer1 transformed features
__device__ __align__(16) float g_out1[(size_t)MAXN * HID];  // layer1 output (post elu)
__device__ __align__(16) float g_as1[MAXN * NH1];
__device__ __align__(16) float g_ad1[MAXN * NH1];
__device__ __align__(16) float g_h2 [(size_t)MAXN * NCLS];
__device__ __align__(16) float g_as2[MAXN];
__device__ __align__(16) float g_ad2[MAXN];
// CSR by destination (shared by both layers)
__device__ int g_deg [MAXN];
__device__ int g_off [MAXN];
__device__ int g_cur [MAXN];
__device__ int g_bsum[1024];
__device__ int g_srcs[MAXET];

// ---------------- init ----------------
__global__ void init_kernel(int N) {
    int i = blockIdx.x * blockDim.x + threadIdx.x;
    if (i < N) g_deg[i] = 0;
}

// ---------------- CSR build ----------------
__global__ void hist_kernel(const int* __restrict__ ei, int E, int ET) {
    int e = blockIdx.x * blockDim.x + threadIdx.x;
    if (e >= ET) return;
    int d = (e < E) ? ei[E + e] : e - E;
    atomicAdd(&g_deg[d], 1);
}

// exclusive scan, 1024-elem blocks
__global__ void scan1_kernel(int N) {
    int i = blockIdx.x * 1024 + threadIdx.x;
    int v = (i < N) ? g_deg[i] : 0;
    int lane = threadIdx.x & 31, wid = threadIdx.x >> 5;
    int x = v;
    #pragma unroll
    for (int o = 1; o < 32; o <<= 1) {
        int y = __shfl_up_sync(0xffffffffu, x, o);
        if (lane >= o) x += y;
    }
    __shared__ int ws[32];
    if (lane == 31) ws[wid] = x;
    __syncthreads();
    if (wid == 0) {
        int w = ws[lane];
        #pragma unroll
        for (int o = 1; o < 32; o <<= 1) {
            int y = __shfl_up_sync(0xffffffffu, w, o);
            if (lane >= o) w += y;
        }
        ws[lane] = w;
    }
    __syncthreads();
    int incl = x + (wid > 0 ? ws[wid - 1] : 0);
    if (i < N) g_off[i] = incl - v;
    if (threadIdx.x == 1023) g_bsum[blockIdx.x] = incl;
}

__global__ void scan2_kernel(int nb) {   // single block, nb <= 1024
    int i = threadIdx.x;
    int v = (i < nb) ? g_bsum[i] : 0;
    int lane = i & 31, wid = i >> 5;
    int x = v;
    #pragma unroll
    for (int o = 1; o < 32; o <<= 1) {
        int y = __shfl_up_sync(0xffffffffu, x, o);
        if (lane >= o) x += y;
    }
    __shared__ int ws[32];
    if (lane == 31) ws[wid] = x;
    __syncthreads();
    if (wid == 0) {
        int w = ws[lane];
        #pragma unroll
        for (int o = 1; o < 32; o <<= 1) {
            int y = __shfl_up_sync(0xffffffffu, w, o);
            if (lane >= o) w += y;
        }
        ws[lane] = w;
    }
    __syncthreads();
    int incl = x + (wid > 0 ? ws[wid - 1] : 0);
    if (i < nb) g_bsum[i] = incl - v;   // exclusive
}

__global__ void scan3_kernel(int N) {
    int i = blockIdx.x * blockDim.x + threadIdx.x;
    if (i >= N) return;
    int o = g_off[i] + g_bsum[i >> 10];
    g_off[i] = o;
    g_cur[i] = o;
}

__global__ void scatter_kernel(const int* __restrict__ ei, int E, int ET) {
    int e = blockIdx.x * blockDim.x + threadIdx.x;
    if (e >= ET) return;
    int s, d;
    if (e < E) { s = ei[e]; d = ei[E + e]; } else { s = e - E; d = s; }
    int pos = atomicAdd(&g_cur[d], 1);
    g_srcs[pos] = s;
}

// ---------------- GEMM1: g_h1[M,256] = x[M,128] @ W1[128,256] ----------------
// BM=128, BN=128, BK=16, 256 threads, 8x8 per thread.
__global__ __launch_bounds__(256) void gemm1_kernel(const float* __restrict__ A,
                                                    const float* __restrict__ B, int M) {
    __shared__ float As[16][132];  // [k][m]
    __shared__ float Bs[16][132];  // [k][n]
    const int t  = threadIdx.x;
    const int tx = t & 15;
    const int ty = t >> 4;
    const int rowBase = blockIdx.y * 128;
    const int colBase = blockIdx.x * 128;
    float acc[8][8];
    #pragma unroll
    for (int i = 0; i < 8; i++)
        #pragma unroll
        for (int j = 0; j < 8; j++) acc[i][j] = 0.f;

    for (int k0 = 0; k0 < F_IN; k0 += 16) {
        #pragma unroll
        for (int i = 0; i < 2; i++) {           // A: 128x16
            int idx = t * 2 + i;
            int r  = idx >> 2;
            int kk = (idx & 3) * 4;
            float4 v = make_float4(0.f, 0.f, 0.f, 0.f);
            int grow = rowBase + r;
            if (grow < M) v = *(const float4*)&A[(size_t)grow * F_IN + k0 + kk];
            As[kk+0][r] = v.x; As[kk+1][r] = v.y; As[kk+2][r] = v.z; As[kk+3][r] = v.w;
        }
        #pragma unroll
        for (int i = 0; i < 2; i++) {           // B: 16x128
            int idx = t * 2 + i;
            int r  = idx >> 5;
            int cc = (idx & 31) * 4;
            float4 v = *(const float4*)&B[(size_t)(k0 + r) * HID + colBase + cc];
            *(float4*)&Bs[r][cc] = v;
        }
        __syncthreads();
        #pragma unroll
        for (int kk = 0; kk < 16; kk++) {
            float4 a0 = *(const float4*)&As[kk][ty * 8];
            float4 a1 = *(const float4*)&As[kk][ty * 8 + 4];
            float4 b0 = *(const float4*)&Bs[kk][tx * 8];
            float4 b1 = *(const float4*)&Bs[kk][tx * 8 + 4];
            float a[8] = {a0.x, a0.y, a0.z, a0.w, a1.x, a1.y, a1.z, a1.w};
            float b[8] = {b0.x, b0.y, b0.z, b0.w, b1.x, b1.y, b1.z, b1.w};
            #pragma unroll
            for (int i = 0; i < 8; i++)
                #pragma unroll
                for (int j = 0; j < 8; j++)
                    acc[i][j] = fmaf(a[i], b[j], acc[i][j]);
        }
        __syncthreads();
    }
    #pragma unroll
    for (int i = 0; i < 8; i++) {
        int r = rowBase + ty * 8 + i;
        if (r >= M) continue;
        float* crow = &g_h1[(size_t)r * HID + colBase + tx * 8];
        *(float4*)crow       = make_float4(acc[i][0], acc[i][1], acc[i][2], acc[i][3]);
        *(float4*)(crow + 4) = make_float4(acc[i][4], acc[i][5], acc[i][6], acc[i][7]);
    }
}

// ---------------- GEMM2: g_h2[M,40] = g_out1[M,256] @ W2[256,40] ----------------
// BM=128, BN=64, BK=16, 256 threads, 8x4 per thread.
__global__ void gemm2_kernel(const float* __restrict__ B, int M) {
    const float* A = g_out1;
    float*       C = g_h2;
    __shared__ float As[16][132];
    __shared__ float Bs[16][68];
    const int t  = threadIdx.x;
    const int tx = t & 15;
    const int ty = t >> 4;
    const int rowBase = blockIdx.y * 128;
    float acc[8][4];
    #pragma unroll
    for (int i = 0; i < 8; i++)
        #pragma unroll
        for (int j = 0; j < 4; j++) acc[i][j] = 0.f;

    for (int k0 = 0; k0 < HID; k0 += 16) {
        #pragma unroll
        for (int i = 0; i < 2; i++) {
            int idx = t * 2 + i;
            int r  = idx >> 2;
            int kk = (idx & 3) * 4;
            float4 v = make_float4(0.f, 0.f, 0.f, 0.f);
            int grow = rowBase + r;
            if (grow < M) v = *(const float4*)&A[(size_t)grow * HID + k0 + kk];
            As[kk+0][r] = v.x; As[kk+1][r] = v.y; As[kk+2][r] = v.z; As[kk+3][r] = v.w;
        }
        {
            int r  = t >> 4;
            int cc = (t & 15) * 4;
            float4 v = make_float4(0.f, 0.f, 0.f, 0.f);
            if (cc < NCLS)
                v = *(const float4*)&B[(size_t)(k0 + r) * NCLS + cc];
            *(float4*)&Bs[r][cc] = v;
        }
        __syncthreads();
        #pragma unroll
        for (int kk = 0; kk < 16; kk++) {
            float4 a0 = *(const float4*)&As[kk][ty * 8];
            float4 a1 = *(const float4*)&As[kk][ty * 8 + 4];
            float4 bv = *(const float4*)&Bs[kk][tx * 4];
            float a[8] = {a0.x, a0.y, a0.z, a0.w, a1.x, a1.y, a1.z, a1.w};
            float b[4] = {bv.x, bv.y, bv.z, bv.w};
            #pragma unroll
            for (int i = 0; i < 8; i++)
                #pragma unroll
                for (int j = 0; j < 4; j++)
                    acc[i][j] = fmaf(a[i], b[j], acc[i][j]);
        }
        __syncthreads();
    }
    #pragma unroll
    for (int i = 0; i < 8; i++) {
        int r = rowBase + ty * 8 + i;
        if (r >= M) continue;
        int c = tx * 4;
        if (c < NCLS)
            *(float4*)&C[(size_t)r * NCLS + c] =
                make_float4(acc[i][0], acc[i][1], acc[i][2], acc[i][3]);
    }
}

// ---------------- attention coefficients ----------------
__global__ void alpha1_kernel(const float* __restrict__ a_src, const float* __restrict__ a_dst, int N) {
    int idx = blockIdx.x * blockDim.x + threadIdx.x;
    if (idx >= N * NH1) return;
    int h = idx & 7;
    const float* row = &g_h1[(size_t)idx * C1];
    float s = 0.f, d = 0.f;
    #pragma unroll
    for (int c = 0; c < C1; c += 4) {
        float4 v  = *(const float4*)&row[c];
        float4 ws = *(const float4*)&a_src[h * C1 + c];
        float4 wd = *(const float4*)&a_dst[h * C1 + c];
        s += v.x*ws.x + v.y*ws.y + v.z*ws.z + v.w*ws.w;
        d += v.x*wd.x + v.y*wd.y + v.z*wd.z + v.w*wd.w;
    }
    g_as1[idx] = s; g_ad1[idx] = d;
}

__global__ void alpha2_kernel(const float* __restrict__ a_src, const float* __restrict__ a_dst, int N) {
    int n = blockIdx.x * blockDim.x + threadIdx.x;
    if (n >= N) return;
    const float* row = &g_h2[(size_t)n * NCLS];
    float s = 0.f, d = 0.f;
    #pragma unroll
    for (int c = 0; c < NCLS; c += 4) {
        float4 v  = *(const float4*)&row[c];
        float4 ws = *(const float4*)&a_src[c];
        float4 wd = *(const float4*)&a_dst[c];
        s += v.x*ws.x + v.y*ws.y + v.z*ws.z + v.w*ws.w;
        d += v.x*wd.x + v.y*wd.y + v.z*wd.z + v.w*wd.w;
    }
    g_as2[n] = s; g_ad2[n] = d;
}

// ---------------- fused layer-1 attention+aggregate+bias+elu ----------------
// one warp per destination node; CSR edge list; no atomics.
__global__ void agg1_kernel(const float* __restrict__ b1, int N) {
    int n = (blockIdx.x * blockDim.x + threadIdx.x) >> 5;
    int lane = threadIdx.x & 31;
    if (n >= N) return;
    int start = g_off[n];
    int deg   = g_deg[n];
    int h     = lane & 7;
    float ad  = g_ad1[n * NH1 + h];

    // pass A: per-head max (4 edges per iteration; lane group lane>>3 handles edge j+group)
    float m = NEG_INF;
    for (int j = 0; j < deg; j += 4) {
        int jj = j + (lane >> 3);
        float e = NEG_INF;
        if (jj < deg) {
            int s = g_srcs[start + jj];
            e = g_as1[s * NH1 + h] + ad;
            e = e >= 0.f ? e : NEGS * e;
        }
        m = fmaxf(m, e);
    }
    m = fmaxf(m, __shfl_xor_sync(0xffffffffu, m, 8));
    m = fmaxf(m, __shfl_xor_sync(0xffffffffu, m, 16));  // lanes 0-7: per-head max

    // pass B: accumulate unnormalized weighted sum + denom
    float acc[NH1];
    #pragma unroll
    for (int k = 0; k < NH1; k++) acc[k] = 0.f;
    float den = 0.f;
    for (int j = 0; j < deg; j++) {
        int s = g_srcs[start + j];
        float ex = 0.f;
        if (lane < NH1) {
            float e = g_as1[s * NH1 + lane] + ad;
            e = e >= 0.f ? e : NEGS * e;
            ex = expf(e - m);
        }
        den += ex;
        const float* hrow = &g_h1[(size_t)s * HID];
        #pragma unroll
        for (int k = 0; k < NH1; k++) {
            float ak = __shfl_sync(0xffffffffu, ex, k);
            acc[k] = fmaf(ak, hrow[k * 32 + lane], acc[k]);
        }
    }
    float* orow = &g_out1[(size_t)n * HID];
    #pragma unroll
    for (int k = 0; k < NH1; k++) {
        float dk = __shfl_sync(0xffffffffu, den, k);
        float v = acc[k] / (dk + 1e-16f) + b1[k * 32 + lane];
        orow[k * 32 + lane] = v > 0.f ? v : expm1f(v);
    }
}

// ---------------- fused layer-2 attention+aggregate+bias+log_softmax ----------------
__global__ void agg2_kernel(const float* __restrict__ b2, float* __restrict__ out, int N) {
    int n = (blockIdx.x * blockDim.x + threadIdx.x) >> 5;
    int lane = threadIdx.x & 31;
    if (n >= N) return;
    int start = g_off[n];
    int deg   = g_deg[n];
    float ad  = g_ad2[n];

    // pass A: scalar max over edges (32 at a time)
    float m = NEG_INF;
    for (int j = 0; j < deg; j += 32) {
        int jj = j + lane;
        float e = NEG_INF;
        if (jj < deg) {
            int s = g_srcs[start + jj];
            e = g_as2[s] + ad;
            e = e >= 0.f ? e : NEGS * e;
        }
        m = fmaxf(m, e);
    }
    #pragma unroll
    for (int o = 16; o > 0; o >>= 1) m = fmaxf(m, __shfl_xor_sync(0xffffffffu, m, o));

    // pass B: accumulate
    float acc_a = 0.f, acc_b = 0.f, den = 0.f;
    for (int j = 0; j < deg; j++) {
        int s = g_srcs[start + j];
        float e = g_as2[s] + ad;
        e = e >= 0.f ? e : NEGS * e;
        float ex = expf(e - m);          // identical across lanes
        den += ex;
        const float* hrow = &g_h2[(size_t)s * NCLS];
        acc_a = fmaf(ex, hrow[lane], acc_a);
        if (lane < NCLS - 32) acc_b = fmaf(ex, hrow[32 + lane], acc_b);
    }
    float inv = 1.f / (den + 1e-16f);
    float oa = acc_a * inv + b2[lane];
    float ob = (lane < NCLS - 32) ? acc_b * inv + b2[32 + lane] : NEG_INF;

    // log_softmax over 40 classes
    float mx = fmaxf(oa, ob);
    #pragma unroll
    for (int o = 16; o > 0; o >>= 1) mx = fmaxf(mx, __shfl_xor_sync(0xffffffffu, mx, o));
    float se = expf(oa - mx) + (lane < NCLS - 32 ? expf(ob - mx) : 0.f);
    #pragma unroll
    for (int o = 16; o > 0; o >>= 1) se += __shfl_xor_sync(0xffffffffu, se, o);
    float l = logf(se);
    float* row = &out[(size_t)n * NCLS];
    row[lane] = oa - mx - l;
    if (lane < NCLS - 32) row[32 + lane] = ob - mx - l;
}

// ---------------- launch ----------------
extern "C" void kernel_launch(void* const* d_in, const int* in_sizes, int n_in,
                              void* d_out, int out_size) {
    const float* x      = (const float*)d_in[0];
    const int*   ei     = (const int*)d_in[1];   // jax int64 silently -> int32 (x64 disabled)
    const float* W1     = (const float*)d_in[2];
    const float* a_src1 = (const float*)d_in[3];
    const float* a_dst1 = (const float*)d_in[4];
    const float* b1     = (const float*)d_in[5];
    const float* W2     = (const float*)d_in[6];
    const float* a_src2 = (const float*)d_in[7];
    const float* a_dst2 = (const float*)d_in[8];
    const float* b2     = (const float*)d_in[9];
    float* out = (float*)d_out;

    int N  = in_sizes[0] / F_IN;
    int E  = in_sizes[1] / 2;
    int ET = E + N;
    int nb = (N + 1023) / 1024;

    init_kernel<<<(N + 255) / 256, 256>>>(N);

    // CSR build (dst-sorted adjacency, shared by both layers)
    hist_kernel<<<(ET + 255) / 256, 256>>>(ei, E, ET);
    scan1_kernel<<<nb, 1024>>>(N);
    scan2_kernel<<<1, 1024>>>(nb);
    scan3_kernel<<<(N + 255) / 256, 256>>>(N);
    scatter_kernel<<<(ET + 255) / 256, 256>>>(ei, E, ET);

    // ---- layer 1 ----
    {
        dim3 g(HID / 128, (N + 127) / 128);
        gemm1_kernel<<<g, 256>>>(x, W1, N);
    }
    alpha1_kernel<<<(N * NH1 + 255) / 256, 256>>>(a_src1, a_dst1, N);
    agg1_kernel<<<(int)(((long long)N * 32 + 255) / 256), 256>>>(b1, N);

    // ---- layer 2 ----
    {
        dim3 g(1, (N + 127) / 128);
        gemm2_kernel<<<g, 256>>>(W2, N);
    }
    alpha2_kernel<<<(N + 255) / 256, 256>>>(a_src2, a_dst2, N);
    agg2_kernel<<<(int)(((long long)N * 32 + 255) / 256), 256>>>(b2, out, N);
}

// round 4
// speedup vs baseline: 2.2968x; 1.4781x over previous
#include <cuda_runtime.h>
#include <math.h>

#define F_IN  128
#define NH1   8
#define C1    32
#define HID   256
#define NCLS  40
#define NEGS  0.2f
#define MAXN  100000
#define MAXET 900000

#define NEG_INF __int_as_float(0xff800000)
#define FULLM 0xffffffffu

// ---------------- scratch (static device globals; no allocation) ----------------
__device__ __align__(16) float g_h1 [(size_t)MAXN * HID];   // layer1 transformed features
__device__ __align__(16) float g_out1[(size_t)MAXN * HID];  // layer1 output (post elu)
__device__ __align__(16) float g_as1[MAXN * NH1];
__device__ __align__(16) float g_ad1[MAXN * NH1];
__device__ __align__(16) float g_h2 [(size_t)MAXN * NCLS];
__device__ __align__(16) float g_as2[MAXN];
__device__ __align__(16) float g_ad2[MAXN];
// CSR by destination (shared by both layers)
__device__ int g_deg [MAXN];
__device__ int g_off [MAXN];
__device__ int g_cur [MAXN];
__device__ int g_bsum[1024];
__device__ int g_srcs[MAXET];

__device__ __forceinline__ float4 fma4(float a, float4 v, float4 c) {
    return make_float4(fmaf(a, v.x, c.x), fmaf(a, v.y, c.y),
                       fmaf(a, v.z, c.z), fmaf(a, v.w, c.w));
}

// ---------------- init ----------------
__global__ void init_kernel(int N) {
    int i = blockIdx.x * blockDim.x + threadIdx.x;
    if (i < N) g_deg[i] = 0;
}

// ---------------- CSR build ----------------
__global__ void hist_kernel(const int* __restrict__ ei, int E, int ET) {
    int e = blockIdx.x * blockDim.x + threadIdx.x;
    if (e >= ET) return;
    int d = (e < E) ? ei[E + e] : e - E;
    atomicAdd(&g_deg[d], 1);
}

// exclusive scan, 1024-elem blocks
__global__ void scan1_kernel(int N) {
    int i = blockIdx.x * 1024 + threadIdx.x;
    int v = (i < N) ? g_deg[i] : 0;
    int lane = threadIdx.x & 31, wid = threadIdx.x >> 5;
    int x = v;
    #pragma unroll
    for (int o = 1; o < 32; o <<= 1) {
        int y = __shfl_up_sync(FULLM, x, o);
        if (lane >= o) x += y;
    }
    __shared__ int ws[32];
    if (lane == 31) ws[wid] = x;
    __syncthreads();
    if (wid == 0) {
        int w = ws[lane];
        #pragma unroll
        for (int o = 1; o < 32; o <<= 1) {
            int y = __shfl_up_sync(FULLM, w, o);
            if (lane >= o) w += y;
        }
        ws[lane] = w;
    }
    __syncthreads();
    int incl = x + (wid > 0 ? ws[wid - 1] : 0);
    if (i < N) g_off[i] = incl - v;
    if (threadIdx.x == 1023) g_bsum[blockIdx.x] = incl;
}

__global__ void scan2_kernel(int nb) {   // single block, nb <= 1024
    int i = threadIdx.x;
    int v = (i < nb) ? g_bsum[i] : 0;
    int lane = i & 31, wid = i >> 5;
    int x = v;
    #pragma unroll
    for (int o = 1; o < 32; o <<= 1) {
        int y = __shfl_up_sync(FULLM, x, o);
        if (lane >= o) x += y;
    }
    __shared__ int ws[32];
    if (lane == 31) ws[wid] = x;
    __syncthreads();
    if (wid == 0) {
        int w = ws[lane];
        #pragma unroll
        for (int o = 1; o < 32; o <<= 1) {
            int y = __shfl_up_sync(FULLM, w, o);
            if (lane >= o) w += y;
        }
        ws[lane] = w;
    }
    __syncthreads();
    int incl = x + (wid > 0 ? ws[wid - 1] : 0);
    if (i < nb) g_bsum[i] = incl - v;   // exclusive
}

__global__ void scan3_kernel(int N) {
    int i = blockIdx.x * blockDim.x + threadIdx.x;
    if (i >= N) return;
    int o = g_off[i] + g_bsum[i >> 10];
    g_off[i] = o;
    g_cur[i] = o;
}

__global__ void scatter_kernel(const int* __restrict__ ei, int E, int ET) {
    int e = blockIdx.x * blockDim.x + threadIdx.x;
    if (e >= ET) return;
    int s, d;
    if (e < E) { s = ei[e]; d = ei[E + e]; } else { s = e - E; d = s; }
    int pos = atomicAdd(&g_cur[d], 1);
    g_srcs[pos] = s;
}

// ---------------- GEMM1: g_h1[M,256] = x[M,128] @ W1[128,256]  (+ fused alpha1) --------
// BM=128, BN=128, BK=16, 256 threads, 8x8 per thread. Each block owns 4 full heads,
// so as1/ad1 for those heads reduce directly from acc registers.
__global__ __launch_bounds__(256) void gemm1_kernel(const float* __restrict__ A,
                                                    const float* __restrict__ B,
                                                    const float* __restrict__ a_src,
                                                    const float* __restrict__ a_dst, int M) {
    __shared__ float As[16][132];  // [k][m]
    __shared__ float Bs[16][132];  // [k][n]
    __shared__ float s_as[128], s_ad[128];
    const int t  = threadIdx.x;
    const int tx = t & 15;
    const int ty = t >> 4;
    const int rowBase = blockIdx.x * 128;
    const int colBase = blockIdx.y * 128;    // 0 -> heads 0-3, 128 -> heads 4-7
    if (t < 128)      s_as[t]       = a_src[colBase + t];
    else              s_ad[t - 128] = a_dst[colBase + t - 128];

    float acc[8][8];
    #pragma unroll
    for (int i = 0; i < 8; i++)
        #pragma unroll
        for (int j = 0; j < 8; j++) acc[i][j] = 0.f;

    for (int k0 = 0; k0 < F_IN; k0 += 16) {
        #pragma unroll
        for (int i = 0; i < 2; i++) {           // A: 128x16
            int idx = t * 2 + i;
            int r  = idx >> 2;
            int kk = (idx & 3) * 4;
            float4 v = make_float4(0.f, 0.f, 0.f, 0.f);
            int grow = rowBase + r;
            if (grow < M) v = *(const float4*)&A[(size_t)grow * F_IN + k0 + kk];
            As[kk+0][r] = v.x; As[kk+1][r] = v.y; As[kk+2][r] = v.z; As[kk+3][r] = v.w;
        }
        #pragma unroll
        for (int i = 0; i < 2; i++) {           // B: 16x128
            int idx = t * 2 + i;
            int r  = idx >> 5;
            int cc = (idx & 31) * 4;
            float4 v = *(const float4*)&B[(size_t)(k0 + r) * HID + colBase + cc];
            *(float4*)&Bs[r][cc] = v;
        }
        __syncthreads();
        #pragma unroll
        for (int kk = 0; kk < 16; kk++) {
            float4 a0 = *(const float4*)&As[kk][ty * 8];
            float4 a1 = *(const float4*)&As[kk][ty * 8 + 4];
            float4 b0 = *(const float4*)&Bs[kk][tx * 8];
            float4 b1 = *(const float4*)&Bs[kk][tx * 8 + 4];
            float a[8] = {a0.x, a0.y, a0.z, a0.w, a1.x, a1.y, a1.z, a1.w};
            float b[8] = {b0.x, b0.y, b0.z, b0.w, b1.x, b1.y, b1.z, b1.w};
            #pragma unroll
            for (int i = 0; i < 8; i++)
                #pragma unroll
                for (int j = 0; j < 8; j++)
                    acc[i][j] = fmaf(a[i], b[j], acc[i][j]);
        }
        __syncthreads();
    }
    const int h0 = colBase >> 5;     // first head of this block
    const int hh = tx >> 2;          // local head of this thread's 8 cols
    #pragma unroll
    for (int i = 0; i < 8; i++) {
        int r = rowBase + ty * 8 + i;
        // alpha partial over this thread's 8 columns
        float ps = 0.f, pd = 0.f;
        #pragma unroll
        for (int j = 0; j < 8; j++) {
            ps = fmaf(acc[i][j], s_as[tx * 8 + j], ps);
            pd = fmaf(acc[i][j], s_ad[tx * 8 + j], pd);
        }
        ps += __shfl_xor_sync(FULLM, ps, 1); ps += __shfl_xor_sync(FULLM, ps, 2);
        pd += __shfl_xor_sync(FULLM, pd, 1); pd += __shfl_xor_sync(FULLM, pd, 2);
        if (r < M) {
            float* crow = &g_h1[(size_t)r * HID + colBase + tx * 8];
            *(float4*)crow       = make_float4(acc[i][0], acc[i][1], acc[i][2], acc[i][3]);
            *(float4*)(crow + 4) = make_float4(acc[i][4], acc[i][5], acc[i][6], acc[i][7]);
            if ((tx & 3) == 0) {
                g_as1[r * NH1 + h0 + hh] = ps;
                g_ad1[r * NH1 + h0 + hh] = pd;
            }
        }
    }
}

// ---------------- GEMM2: g_h2[M,40] = g_out1[M,256] @ W2[256,40] (+ fused alpha2) -----
// BM=128, BN=64(40 used), BK=16, 256 threads, 8x4 per thread.
__global__ void gemm2_kernel(const float* __restrict__ B,
                             const float* __restrict__ a_src,
                             const float* __restrict__ a_dst, int M) {
    const float* A = g_out1;
    float*       C = g_h2;
    __shared__ float As[16][132];
    __shared__ float Bs[16][68];
    __shared__ float s_s[64], s_d[64];
    const int t  = threadIdx.x;
    const int tx = t & 15;
    const int ty = t >> 4;
    const int rowBase = blockIdx.x * 128;
    if (t < NCLS) { s_s[t] = a_src[t]; s_d[t] = a_dst[t]; }
    else if (t < 64) { s_s[t] = 0.f; s_d[t] = 0.f; }

    float acc[8][4];
    #pragma unroll
    for (int i = 0; i < 8; i++)
        #pragma unroll
        for (int j = 0; j < 4; j++) acc[i][j] = 0.f;

    for (int k0 = 0; k0 < HID; k0 += 16) {
        #pragma unroll
        for (int i = 0; i < 2; i++) {
            int idx = t * 2 + i;
            int r  = idx >> 2;
            int kk = (idx & 3) * 4;
            float4 v = make_float4(0.f, 0.f, 0.f, 0.f);
            int grow = rowBase + r;
            if (grow < M) v = *(const float4*)&A[(size_t)grow * HID + k0 + kk];
            As[kk+0][r] = v.x; As[kk+1][r] = v.y; As[kk+2][r] = v.z; As[kk+3][r] = v.w;
        }
        {
            int r  = t >> 4;
            int cc = (t & 15) * 4;
            float4 v = make_float4(0.f, 0.f, 0.f, 0.f);
            if (cc < NCLS)
                v = *(const float4*)&B[(size_t)(k0 + r) * NCLS + cc];
            *(float4*)&Bs[r][cc] = v;
        }
        __syncthreads();
        #pragma unroll
        for (int kk = 0; kk < 16; kk++) {
            float4 a0 = *(const float4*)&As[kk][ty * 8];
            float4 a1 = *(const float4*)&As[kk][ty * 8 + 4];
            float4 bv = *(const float4*)&Bs[kk][tx * 4];
            float a[8] = {a0.x, a0.y, a0.z, a0.w, a1.x, a1.y, a1.z, a1.w};
            float b[4] = {bv.x, bv.y, bv.z, bv.w};
            #pragma unroll
            for (int i = 0; i < 8; i++)
                #pragma unroll
                for (int j = 0; j < 4; j++)
                    acc[i][j] = fmaf(a[i], b[j], acc[i][j]);
        }
        __syncthreads();
    }
    #pragma unroll
    for (int i = 0; i < 8; i++) {
        int r = rowBase + ty * 8 + i;
        float ps = 0.f, pd = 0.f;
        #pragma unroll
        for (int j = 0; j < 4; j++) {
            ps = fmaf(acc[i][j], s_s[tx * 4 + j], ps);
            pd = fmaf(acc[i][j], s_d[tx * 4 + j], pd);
        }
        #pragma unroll
        for (int o = 1; o < 16; o <<= 1) {
            ps += __shfl_xor_sync(FULLM, ps, o);
            pd += __shfl_xor_sync(FULLM, pd, o);
        }
        if (r < M) {
            int c = tx * 4;
            if (c < NCLS)
                *(float4*)&C[(size_t)r * NCLS + c] =
                    make_float4(acc[i][0], acc[i][1], acc[i][2], acc[i][3]);
            if (tx == 0) { g_as2[r] = ps; g_ad2[r] = pd; }
        }
    }
}

// ---------------- fused layer-1 attention+aggregate+bias+elu ----------------
// one warp per destination; single pass (no max subtraction — logits are O(3)).
__global__ void agg1_kernel(const float* __restrict__ b1, int N) {
    int n = (blockIdx.x * blockDim.x + threadIdx.x) >> 5;
    int lane = threadIdx.x & 31;
    if (n >= N) return;
    int start = g_off[n];
    int deg   = g_deg[n];
    float ad  = g_ad1[n * NH1 + (lane & 7)];
    const int hsel = lane >> 3;   // head selector for first 128 channels

    float4 acc0 = make_float4(0.f, 0.f, 0.f, 0.f);
    float4 acc1 = make_float4(0.f, 0.f, 0.f, 0.f);
    float den = 0.f;
    int j = 0;
    for (; j + 2 <= deg; j += 2) {
        int s0 = g_srcs[start + j];
        int s1 = g_srcs[start + j + 1];
        float ex0 = 0.f, ex1 = 0.f;
        if (lane < NH1) {
            float e0 = g_as1[s0 * NH1 + lane] + ad;
            float e1 = g_as1[s1 * NH1 + lane] + ad;
            e0 = e0 >= 0.f ? e0 : NEGS * e0;
            e1 = e1 >= 0.f ? e1 : NEGS * e1;
            ex0 = __expf(e0); ex1 = __expf(e1);
        }
        den += ex0 + ex1;
        const float4* h0p = (const float4*)&g_h1[(size_t)s0 * HID];
        const float4* h1p = (const float4*)&g_h1[(size_t)s1 * HID];
        float4 v00 = h0p[lane], v01 = h0p[32 + lane];
        float4 v10 = h1p[lane], v11 = h1p[32 + lane];
        float a00 = __shfl_sync(FULLM, ex0, hsel);
        float a01 = __shfl_sync(FULLM, ex0, 4 + hsel);
        float a10 = __shfl_sync(FULLM, ex1, hsel);
        float a11 = __shfl_sync(FULLM, ex1, 4 + hsel);
        acc0 = fma4(a00, v00, acc0); acc0 = fma4(a10, v10, acc0);
        acc1 = fma4(a01, v01, acc1); acc1 = fma4(a11, v11, acc1);
    }
    if (j < deg) {
        int s0 = g_srcs[start + j];
        float ex0 = 0.f;
        if (lane < NH1) {
            float e0 = g_as1[s0 * NH1 + lane] + ad;
            e0 = e0 >= 0.f ? e0 : NEGS * e0;
            ex0 = __expf(e0);
        }
        den += ex0;
        const float4* h0p = (const float4*)&g_h1[(size_t)s0 * HID];
        float4 v00 = h0p[lane], v01 = h0p[32 + lane];
        float a00 = __shfl_sync(FULLM, ex0, hsel);
        float a01 = __shfl_sync(FULLM, ex0, 4 + hsel);
        acc0 = fma4(a00, v00, acc0);
        acc1 = fma4(a01, v01, acc1);
    }
    float i0 = 1.f / (__shfl_sync(FULLM, den, hsel)     + 1e-16f);
    float i1 = 1.f / (__shfl_sync(FULLM, den, 4 + hsel) + 1e-16f);
    const float4* b4 = (const float4*)b1;
    float4 bb0 = b4[lane], bb1 = b4[32 + lane];
    float4 o0 = make_float4(acc0.x * i0 + bb0.x, acc0.y * i0 + bb0.y,
                            acc0.z * i0 + bb0.z, acc0.w * i0 + bb0.w);
    float4 o1 = make_float4(acc1.x * i1 + bb1.x, acc1.y * i1 + bb1.y,
                            acc1.z * i1 + bb1.z, acc1.w * i1 + bb1.w);
    o0.x = o0.x > 0.f ? o0.x : expm1f(o0.x);
    o0.y = o0.y > 0.f ? o0.y : expm1f(o0.y);
    o0.z = o0.z > 0.f ? o0.z : expm1f(o0.z);
    o0.w = o0.w > 0.f ? o0.w : expm1f(o0.w);
    o1.x = o1.x > 0.f ? o1.x : expm1f(o1.x);
    o1.y = o1.y > 0.f ? o1.y : expm1f(o1.y);
    o1.z = o1.z > 0.f ? o1.z : expm1f(o1.z);
    o1.w = o1.w > 0.f ? o1.w : expm1f(o1.w);
    float4* orow = (float4*)&g_out1[(size_t)n * HID];
    orow[lane]      = o0;
    orow[32 + lane] = o1;
}

// ---------------- fused layer-2 attention+aggregate+bias+log_softmax ----------------
__global__ void agg2_kernel(const float* __restrict__ b2, float* __restrict__ out, int N) {
    int n = (blockIdx.x * blockDim.x + threadIdx.x) >> 5;
    int lane = threadIdx.x & 31;
    if (n >= N) return;
    int start = g_off[n];
    int deg   = g_deg[n];
    float ad  = g_ad2[n];
    const bool act = lane < (NCLS / 4);   // lanes 0-9 hold 4 cols each

    float4 acc = make_float4(0.f, 0.f, 0.f, 0.f);
    float den = 0.f;
    int j = 0;
    for (; j + 2 <= deg; j += 2) {
        int s0 = g_srcs[start + j];
        int s1 = g_srcs[start + j + 1];
        float e0 = g_as2[s0] + ad;  e0 = e0 >= 0.f ? e0 : NEGS * e0;
        float e1 = g_as2[s1] + ad;  e1 = e1 >= 0.f ? e1 : NEGS * e1;
        float ex0 = __expf(e0), ex1 = __expf(e1);
        den += ex0 + ex1;
        if (act) {
            float4 v0 = ((const float4*)&g_h2[(size_t)s0 * NCLS])[lane];
            float4 v1 = ((const float4*)&g_h2[(size_t)s1 * NCLS])[lane];
            acc = fma4(ex0, v0, acc);
            acc = fma4(ex1, v1, acc);
        }
    }
    if (j < deg) {
        int s0 = g_srcs[start + j];
        float e0 = g_as2[s0] + ad;  e0 = e0 >= 0.f ? e0 : NEGS * e0;
        float ex0 = __expf(e0);
        den += ex0;
        if (act) {
            float4 v0 = ((const float4*)&g_h2[(size_t)s0 * NCLS])[lane];
            acc = fma4(ex0, v0, acc);
        }
    }
    float inv = 1.f / (den + 1e-16f);
    float4 o = make_float4(0.f, 0.f, 0.f, 0.f);
    if (act) {
        float4 bb = ((const float4*)b2)[lane];
        o = make_float4(acc.x * inv + bb.x, acc.y * inv + bb.y,
                        acc.z * inv + bb.z, acc.w * inv + bb.w);
    }
    // log_softmax over 40 classes
    float mx = act ? fmaxf(fmaxf(o.x, o.y), fmaxf(o.z, o.w)) : NEG_INF;
    #pragma unroll
    for (int s = 16; s > 0; s >>= 1) mx = fmaxf(mx, __shfl_xor_sync(FULLM, mx, s));
    float se = act ? (__expf(o.x - mx) + __expf(o.y - mx) + __expf(o.z - mx) + __expf(o.w - mx)) : 0.f;
    #pragma unroll
    for (int s = 16; s > 0; s >>= 1) se += __shfl_xor_sync(FULLM, se, s);
    float l = mx + logf(se);
    if (act)
        ((float4*)&out[(size_t)n * NCLS])[lane] =
            make_float4(o.x - l, o.y - l, o.z - l, o.w - l);
}

// ---------------- launch ----------------
extern "C" void kernel_launch(void* const* d_in, const int* in_sizes, int n_in,
                              void* d_out, int out_size) {
    const float* x      = (const float*)d_in[0];
    const int*   ei     = (const int*)d_in[1];   // jax int64 silently -> int32 (x64 disabled)
    const float* W1     = (const float*)d_in[2];
    const float* a_src1 = (const float*)d_in[3];
    const float* a_dst1 = (const float*)d_in[4];
    const float* b1     = (const float*)d_in[5];
    const float* W2     = (const float*)d_in[6];
    const float* a_src2 = (const float*)d_in[7];
    const float* a_dst2 = (const float*)d_in[8];
    const float* b2     = (const float*)d_in[9];
    float* out = (float*)d_out;

    int N  = in_sizes[0] / F_IN;
    int E  = in_sizes[1] / 2;
    int ET = E + N;
    int nb = (N + 1023) / 1024;

    init_kernel<<<(N + 255) / 256, 256>>>(N);

    // CSR build (dst-sorted adjacency, shared by both layers)
    hist_kernel<<<(ET + 255) / 256, 256>>>(ei, E, ET);
    scan1_kernel<<<nb, 1024>>>(N);
    scan2_kernel<<<1, 1024>>>(nb);
    scan3_kernel<<<(N + 255) / 256, 256>>>(N);
    scatter_kernel<<<(ET + 255) / 256, 256>>>(ei, E, ET);

    // ---- layer 1 ----
    {
        dim3 g((N + 127) / 128, HID / 128);
        gemm1_kernel<<<g, 256>>>(x, W1, a_src1, a_dst1, N);
    }
    agg1_kernel<<<(int)(((long long)N * 32 + 255) / 256), 256>>>(b1, N);

    // ---- layer 2 ----
    gemm2_kernel<<<(N + 127) / 128, 256>>>(W2, a_src2, a_dst2, N);
    agg2_kernel<<<(int)(((long long)N * 32 + 255) / 256), 256>>>(b2, out, N);
}